// round 5
// baseline (speedup 1.0000x reference)
#include <cuda_runtime.h>
#include <cuda_bf16.h>
#include <math_constants.h>
#include <cstdint>

typedef unsigned long long ull;
typedef __nv_bfloat16 bf16;

#define BATCH   16
#define SEQT    256
#define DMODEL  2048
#define NHEADS  32
#define HDIM    64
#define SKTOT   512
#define MTOT    (BATCH*SEQT)          // 4096

// d_out layout: [out (B,T,D)][new_k (B,H,512,64)][new_v (B,H,512,64)]
#define OFF_NEWK (16ull*256*2048)                 // 8,388,608
#define OFF_NEWV (OFF_NEWK + 16ull*32*512*64)     // 25,165,824

// ---------------- scratch (static device arrays; no runtime allocation) ----------------
__device__ __align__(256) float g_q   [BATCH*NHEADS*SEQT*HDIM];   // rotated q  [B,H,T,Hd]
__device__ __align__(256) float g_krot[BATCH*NHEADS*SEQT*HDIM];   // rotated cur_k
__device__ __align__(256) float g_attn[BATCH*SEQT*DMODEL];        // attn out   [B,T,D]

// bf16 split operands (hi/lo)
__device__ __align__(256) bf16 g_xh[MTOT*DMODEL],    g_xl[MTOT*DMODEL];
__device__ __align__(256) bf16 g_ah[MTOT*DMODEL],    g_al[MTOT*DMODEL];
__device__ __align__(256) bf16 g_wqh[DMODEL*DMODEL], g_wql[DMODEL*DMODEL];
__device__ __align__(256) bf16 g_wkh[DMODEL*DMODEL], g_wkl[DMODEL*DMODEL];
__device__ __align__(256) bf16 g_wvh[DMODEL*DMODEL], g_wvl[DMODEL*DMODEL];
__device__ __align__(256) bf16 g_woh[DMODEL*DMODEL], g_wol[DMODEL*DMODEL];

// ---------------- PTX helpers (base-ISA only: no 'a'-gated instructions) ----------------
__device__ __forceinline__ uint32_t smem_u32(const void* p){
    uint32_t a;
    asm("{ .reg .u64 t; cvta.to.shared.u64 t, %1; cvt.u32.u64 %0, t; }" : "=r"(a) : "l"(p));
    return a;
}
__device__ __forceinline__ void cpasync16(uint32_t dst, const void* src){
    asm volatile("cp.async.cg.shared.global [%0], [%1], 16;" :: "r"(dst), "l"(src));
}
#define CP_COMMIT() asm volatile("cp.async.commit_group;" ::: "memory")
#define CP_WAIT1()  asm volatile("cp.async.wait_group 1;"  ::: "memory")
#define CP_WAIT0()  asm volatile("cp.async.wait_group 0;"  ::: "memory")

__device__ __forceinline__ void ldsm4(uint32_t& r0, uint32_t& r1, uint32_t& r2, uint32_t& r3,
                                      uint32_t addr){
    asm volatile("ldmatrix.sync.aligned.m8n8.x4.shared.b16 {%0,%1,%2,%3}, [%4];"
        : "=r"(r0), "=r"(r1), "=r"(r2), "=r"(r3) : "r"(addr));
}
__device__ __forceinline__ void mma16816(float* d, const uint32_t* a, const uint32_t* b){
    asm volatile("mma.sync.aligned.m16n8k16.row.col.f32.bf16.bf16.f32 "
        "{%0,%1,%2,%3}, {%4,%5,%6,%7}, {%8,%9}, {%0,%1,%2,%3};"
        : "+f"(d[0]), "+f"(d[1]), "+f"(d[2]), "+f"(d[3])
        : "r"(a[0]), "r"(a[1]), "r"(a[2]), "r"(a[3]), "r"(b[0]), "r"(b[1]));
}

// ---------------- fp32 -> bf16 hi/lo split ----------------
// mode: 0=x, 1=Wq, 2=Wk, 3=Wv, 4=Wo, 5=g_attn (dst selected device-side)
__global__ void conv_split(const float* __restrict__ s, int mode, int n4){
    int i = blockIdx.x*blockDim.x + threadIdx.x;
    if (i >= n4) return;
    bf16 *h, *l;
    switch (mode){
        case 0:  h = g_xh;  l = g_xl;  break;
        case 1:  h = g_wqh; l = g_wql; break;
        case 2:  h = g_wkh; l = g_wkl; break;
        case 3:  h = g_wvh; l = g_wvl; break;
        case 4:  h = g_woh; l = g_wol; break;
        default: h = g_ah;  l = g_al;  s = g_attn; break;
    }
    float4 v = ((const float4*)s)[i];
    bf16 h0 = __float2bfloat16(v.x), h1 = __float2bfloat16(v.y);
    bf16 h2 = __float2bfloat16(v.z), h3 = __float2bfloat16(v.w);
    bf16 l0 = __float2bfloat16(v.x - __bfloat162float(h0));
    bf16 l1 = __float2bfloat16(v.y - __bfloat162float(h1));
    bf16 l2 = __float2bfloat16(v.z - __bfloat162float(h2));
    bf16 l3 = __float2bfloat16(v.w - __bfloat162float(h3));
    ((__nv_bfloat162*)h)[2*i]   = __nv_bfloat162(h0, h1);
    ((__nv_bfloat162*)h)[2*i+1] = __nv_bfloat162(h2, h3);
    ((__nv_bfloat162*)l)[2*i]   = __nv_bfloat162(l0, l1);
    ((__nv_bfloat162*)l)[2*i+1] = __nv_bfloat162(l2, l3);
}

// ---------------- mma.sync split-bf16 NT GEMM ----------------
// C[m,n] = sum_k A[m,k]*W[n,k]; both K-major bf16 hi/lo. 3 terms (hh,hl,lh), ll dropped.
// CTA 128x128, BK=64, double-buffered cp.async, 8 warps @ 64x32 warp tiles.
#define BM 128
#define BN 128
#define BK 64
#define NCHUNK (DMODEL/BK)          // 32
#define TILE_B  (128*128)           // 16384 bytes: 128 rows x 64 bf16 (128B/row)
#define STAGE_B (4*TILE_B)          // Ah,Al,Bh,Bl = 65536
#define SMEM_TOTAL (2*STAGE_B)      // 131072

// mode: 0=Q, 1=K, 2=V (fused over blockIdx.z), 3=output projection
__global__ __launch_bounds__(256, 1) void gemm_mma_kernel(float* __restrict__ dout, int mode_base){
    extern __shared__ char smem[];
    const uint32_t sb = smem_u32(smem);
    const int tid  = threadIdx.x;
    const int wid  = tid >> 5;
    const int lane = tid & 31;
    const int m0   = blockIdx.y * BM;
    const int n0   = blockIdx.x * BN;
    const int mode = (mode_base == 0) ? (int)blockIdx.z : 3;

    const bf16 *Ah, *Al, *Wh, *Wl;
    if (mode == 3){ Ah = g_ah; Al = g_al; Wh = g_woh; Wl = g_wol; }
    else {
        Ah = g_xh; Al = g_xl;
        Wh = (mode==0) ? g_wqh : (mode==1 ? g_wkh : g_wvh);
        Wl = (mode==0) ? g_wql : (mode==1 ? g_wkl : g_wvl);
    }

    // warp tiling: 2 (m) x 4 (n) warps; warp tile 64 x 32
    const int mwarp = (wid & 1) * 64;
    const int nwarp = (wid >> 1) * 32;
    const int g  = lane >> 3;     // ldmatrix matrix group 0..3
    const int li = lane & 7;      // row within 8x8 matrix

    float acc[4][4][4];
    #pragma unroll
    for (int a = 0; a < 4; a++)
        #pragma unroll
        for (int b = 0; b < 4; b++)
            #pragma unroll
            for (int c = 0; c < 4; c++) acc[a][b][c] = 0.f;

    // chunk loader: 16 cp.async/thread (4 per operand tile), K-major rows, SW128
    auto load_chunk = [&](int c, int s){
        const int k0 = c * BK;
        const uint32_t stb = sb + s*STAGE_B;
        #pragma unroll
        for (int t = 0; t < 4; t++){
            int idx = tid + t*256;          // 0..1023
            int r = idx >> 3, cg = idx & 7; // row 0..127, 16B group along k
            uint32_t sw = (uint32_t)(r*128 + (((uint32_t)(cg*16)) ^ ((r & 7) << 4)));
            const bf16* a_h = Ah + (size_t)(m0+r)*DMODEL + k0 + cg*8;
            const bf16* a_l = Al + (size_t)(m0+r)*DMODEL + k0 + cg*8;
            const bf16* b_h = Wh + (size_t)(n0+r)*DMODEL + k0 + cg*8;
            const bf16* b_l = Wl + (size_t)(n0+r)*DMODEL + k0 + cg*8;
            cpasync16(stb + 0*TILE_B + sw, a_h);
            cpasync16(stb + 1*TILE_B + sw, a_l);
            cpasync16(stb + 2*TILE_B + sw, b_h);
            cpasync16(stb + 3*TILE_B + sw, b_l);
        }
        CP_COMMIT();
    };

    load_chunk(0, 0);

    for (int c = 0; c < NCHUNK; c++){
        if (c + 1 < NCHUNK){ load_chunk(c + 1, (c + 1) & 1); CP_WAIT1(); }
        else               { CP_WAIT0(); }
        __syncthreads();

        const uint32_t stb = sb + (c & 1)*STAGE_B;
        const uint32_t bAh = stb + 0*TILE_B, bAl = stb + 1*TILE_B;
        const uint32_t bBh = stb + 2*TILE_B, bBl = stb + 3*TILE_B;

        #pragma unroll
        for (int k16 = 0; k16 < 4; k16++){
            // A fragments: lane groups g -> (m + (g&1)*8, k + (g>>1)*8)
            uint32_t ah[4][4], al[4][4];
            {
                const uint32_t colA = (uint32_t)(k16*32 + (g >> 1)*16);
                #pragma unroll
                for (int mt = 0; mt < 4; mt++){
                    uint32_t rowA = (uint32_t)(mwarp + mt*16 + (g & 1)*8 + li);
                    uint32_t off  = rowA*128 + (colA ^ ((rowA & 7) << 4));
                    ldsm4(ah[mt][0], ah[mt][1], ah[mt][2], ah[mt][3], bAh + off);
                    ldsm4(al[mt][0], al[mt][1], al[mt][2], al[mt][3], bAl + off);
                }
            }
            // B fragments: lane groups g -> (n + (g>>1)*8, k + (g&1)*8)
            uint32_t bh[4][2], bl[4][2];
            {
                const uint32_t colB = (uint32_t)(k16*32 + (g & 1)*16);
                #pragma unroll
                for (int nt2 = 0; nt2 < 2; nt2++){
                    uint32_t rowB = (uint32_t)(nwarp + nt2*16 + (g >> 1)*8 + li);
                    uint32_t off  = rowB*128 + (colB ^ ((rowB & 7) << 4));
                    ldsm4(bh[nt2*2][0], bh[nt2*2][1], bh[nt2*2+1][0], bh[nt2*2+1][1], bBh + off);
                    ldsm4(bl[nt2*2][0], bl[nt2*2][1], bl[nt2*2+1][0], bl[nt2*2+1][1], bBl + off);
                }
            }
            #pragma unroll
            for (int mt = 0; mt < 4; mt++)
                #pragma unroll
                for (int nt = 0; nt < 4; nt++){
                    mma16816(acc[mt][nt], ah[mt], bh[nt]);   // hh
                    mma16816(acc[mt][nt], ah[mt], bl[nt]);   // hl
                    mma16816(acc[mt][nt], al[mt], bh[nt]);   // lh
                }
        }
        __syncthreads();
    }

    // epilogue: c0,c1 at (m, n..n+1); c2,c3 at (m+8, n..n+1)
    #pragma unroll
    for (int mt = 0; mt < 4; mt++){
        #pragma unroll
        for (int nt = 0; nt < 4; nt++){
            int m = m0 + mwarp + mt*16 + (lane >> 2);
            int n = n0 + nwarp + nt*8  + (lane & 3)*2;
            #pragma unroll
            for (int half = 0; half < 2; half++){
                int mm = m + half*8;
                float2 v = make_float2(acc[mt][nt][half*2], acc[mt][nt][half*2+1]);
                if (mode == 3){
                    *(float2*)(dout + (size_t)mm*DMODEL + n) = v;
                } else {
                    int b = mm >> 8, t = mm & 255, h = n >> 6, d = n & 63;
                    if (mode == 0){
                        *(float2*)(g_q + (((size_t)(b*NHEADS + h)*SEQT + t)*HDIM + d)) = v;
                    } else {
                        float* base = dout + (mode==1 ? OFF_NEWK : OFF_NEWV);
                        *(float2*)(base + (((size_t)(b*NHEADS + h)*SKTOT + 256 + t)*HDIM + d)) = v;
                    }
                }
            }
        }
    }
}

// ---------------- cache copy: past[256:512] -> new[0:256] ----------------
__global__ void copy_past_kernel(const float* __restrict__ past_k,
                                 const float* __restrict__ past_v,
                                 float* __restrict__ dout){
    int idx = blockIdx.x*blockDim.x + threadIdx.x;      // float4 units
    const int N4 = BATCH*NHEADS*SEQT*HDIM/4;
    if (idx >= 2*N4) return;
    int sel = idx >= N4;
    int e = sel ? idx - N4 : idx;
    int d4 = e & 15, t = (e >> 4) & 255, bh = e >> 12;
    size_t src = ((size_t)bh*SKTOT + 256 + t)*16 + d4;
    size_t dst = ((size_t)bh*SKTOT + t)*16 + d4;
    const float4* s = sel ? (const float4*)past_v : (const float4*)past_k;
    float4* dp = (float4*)(dout + (sel ? OFF_NEWV : OFF_NEWK));
    dp[dst] = s[src];
}

// ---------------- RoPE: q in place; cur_k (from new_k[256:]) -> g_krot ----------------
__global__ void rope_kernel(const int* __restrict__ pos_ptr, float* __restrict__ dout){
    int idx = blockIdx.x*blockDim.x + threadIdx.x;
    const int NP = BATCH*NHEADS*SEQT*(HDIM/2);
    if (idx >= 2*NP) return;
    int isk = idx >= NP;
    int i = isk ? idx - NP : idx;
    int p  = i & 31;
    int t  = (i >> 5) & 255;
    int bh = i >> 13;
    int pos = *pos_ptr + t;
    float inv = exp2f(-(float)p * (13.2877123795494f / 32.0f));  // 10000^(-p/32)
    float ang = (float)pos * inv;
    float s, c;
    sincosf(ang, &s, &c);
    if (!isk){
        float* q = g_q + (((size_t)bh*SEQT + t)*HDIM + 2*p);
        float a = q[0], b = q[1];
        q[0] = a*c - b*s;
        q[1] = a*s + b*c;
    } else {
        const float* ks = dout + OFF_NEWK + (((size_t)bh*SKTOT + 256 + t)*HDIM + 2*p);
        float a = ks[0], b = ks[1];
        float* kd = g_krot + (((size_t)bh*SEQT + t)*HDIM + 2*p);
        kd[0] = a*c - b*s;
        kd[1] = a*s + b*c;
    }
}

// ---------------- flash attention (FFMA2), block=(b,h), thread=query row ----------------
__device__ __forceinline__ ull pack2(float lo, float hi){
    ull r; asm("mov.b64 %0, {%1, %2};" : "=l"(r) : "f"(lo), "f"(hi)); return r;
}
__device__ __forceinline__ float2 unpack2(ull v){
    float2 r; asm("mov.b64 {%0, %1}, %2;" : "=f"(r.x), "=f"(r.y) : "l"(v)); return r;
}
__device__ __forceinline__ void fma2(ull& d, ull a, ull b){
    asm("fma.rn.f32x2 %0, %1, %2, %0;" : "+l"(d) : "l"(a), "l"(b));
}
__device__ __forceinline__ void mul2(ull& d, ull a){
    asm("mul.rn.f32x2 %0, %0, %1;" : "+l"(d) : "l"(a));
}

__global__ __launch_bounds__(256,1) void attn_kernel(const float* __restrict__ dout){
    const float* newk = dout + OFF_NEWK;
    const float* newv = dout + OFF_NEWV;
    const int bh = blockIdx.x;
    const int tid = threadIdx.x;

    __shared__ float ks[32][68];
    __shared__ float vs[32][68];

    ull q2[32];
    {
        const float* qrow = g_q + ((size_t)bh*SEQT + tid)*HDIM;
        #pragma unroll
        for (int d4 = 0; d4 < 16; d4++){
            ulonglong2 tt = *(const ulonglong2*)(qrow + 4*d4);
            q2[2*d4] = tt.x; q2[2*d4+1] = tt.y;
        }
    }
    ull acc[32];
    #pragma unroll
    for (int d2 = 0; d2 < 32; d2++) acc[d2] = 0ull;
    float mmax = -CUDART_INF_F, lsum = 0.f;

    for (int kt = 0; kt < 16; kt++){
        const int j0 = kt*32;
        #pragma unroll
        for (int e = 0; e < 2; e++){
            int ee = tid + e*256;
            int jj = ee >> 4, d4 = ee & 15;
            int j = j0 + jj;
            const float* ksrc = (j < SEQT)
                ? (newk + ((size_t)bh*SKTOT + j)*HDIM)
                : (g_krot + ((size_t)bh*SEQT + (j - SEQT))*HDIM);
            *(float4*)&ks[jj][d4*4] = *(const float4*)(ksrc + d4*4);
            *(float4*)&vs[jj][d4*4] = *(const float4*)(newv + ((size_t)bh*SKTOT + j)*HDIM + d4*4);
        }
        __syncthreads();

        if (j0 <= tid + 256){   // tile has >=1 visible key for this query row
            float s[32];
            #pragma unroll
            for (int jj = 0; jj < 32; jj++){
                ull a2 = 0ull;
                #pragma unroll
                for (int d2 = 0; d2 < 32; d2++){
                    ull k2 = *(const ull*)&ks[jj][2*d2];
                    fma2(a2, q2[d2], k2);
                }
                float2 f = unpack2(a2);
                s[jj] = (f.x + f.y) * 0.125f;
            }
            if (j0 >= 256){     // causal mask only matters in second half
                #pragma unroll
                for (int jj = 0; jj < 32; jj++)
                    if (j0 + jj > tid + 256) s[jj] = -CUDART_INF_F;
            }
            float tmax = s[0];
            #pragma unroll
            for (int jj = 1; jj < 32; jj++) tmax = fmaxf(tmax, s[jj]);
            float mnew  = fmaxf(mmax, tmax);
            float alpha = __expf(mmax - mnew);
            lsum *= alpha;
            ull al = pack2(alpha, alpha);
            #pragma unroll
            for (int d2 = 0; d2 < 32; d2++) mul2(acc[d2], al);
            #pragma unroll
            for (int jj = 0; jj < 32; jj++){
                float p = __expf(s[jj] - mnew);
                lsum += p;
                ull pp = pack2(p, p);
                #pragma unroll
                for (int d2 = 0; d2 < 32; d2++){
                    ull v2 = *(const ull*)&vs[jj][2*d2];
                    fma2(acc[d2], pp, v2);
                }
            }
            mmax = mnew;
        }
        __syncthreads();
    }

    const float inv = 1.0f / lsum;
    const int b = bh >> 5, h = bh & 31;
    float* orow = g_attn + ((size_t)(b*SEQT + tid))*DMODEL + h*HDIM;
    #pragma unroll
    for (int d2 = 0; d2 < 32; d2++){
        float2 f = unpack2(acc[d2]);
        orow[2*d2]   = f.x * inv;
        orow[2*d2+1] = f.y * inv;
    }
}

// ---------------- launch ----------------
extern "C" void kernel_launch(void* const* d_in, const int* in_sizes, int n_in,
                              void* d_out, int out_size)
{
    const float* x      = (const float*)d_in[0];
    const float* past_k = (const float*)d_in[1];
    const float* past_v = (const float*)d_in[2];
    const float* Wq     = (const float*)d_in[3];
    const float* Wk     = (const float*)d_in[4];
    const float* Wv     = (const float*)d_in[5];
    const float* Wo     = (const float*)d_in[6];
    const int*   pos    = (const int*)d_in[7];
    float* out = (float*)d_out;

    cudaFuncSetAttribute(gemm_mma_kernel, cudaFuncAttributeMaxDynamicSharedMemorySize, SMEM_TOTAL);

    // 0) bf16 hi/lo splits of x and all four weights
    {
        int nx4 = MTOT*DMODEL/4;
        conv_split<<<(nx4+255)/256, 256>>>(x,  0, nx4);
        int nw4 = DMODEL*DMODEL/4;
        conv_split<<<(nw4+255)/256, 256>>>(Wq, 1, nw4);
        conv_split<<<(nw4+255)/256, 256>>>(Wk, 2, nw4);
        conv_split<<<(nw4+255)/256, 256>>>(Wv, 3, nw4);
        conv_split<<<(nw4+255)/256, 256>>>(Wo, 4, nw4);
    }

    // 1) fused QKV projections (z = 0/1/2 -> Q/K/V)
    {
        dim3 gg(DMODEL/BN, MTOT/BM, 3);
        gemm_mma_kernel<<<gg, 256, SMEM_TOTAL>>>(out, 0);
    }

    // 2) fill new_k/new_v[0:256] from past[256:512]
    {
        int n = 2*BATCH*NHEADS*SEQT*HDIM/4;
        copy_past_kernel<<<(n + 255)/256, 256>>>(past_k, past_v, out);
    }

    // 3) RoPE
    {
        int n = 2*BATCH*NHEADS*SEQT*(HDIM/2);
        rope_kernel<<<(n + 255)/256, 256>>>(pos, out);
    }

    // 4) attention
    attn_kernel<<<BATCH*NHEADS, 256>>>(out);

    // 5) output projection: split g_attn, then GEMM -> d_out[0 : B*T*D]
    {
        int na4 = MTOT*DMODEL/4;
        conv_split<<<(na4+255)/256, 256>>>(nullptr, 5, na4);   // src = g_attn
        dim3 gg(DMODEL/BN, MTOT/BM, 1);
        gemm_mma_kernel<<<gg, 256, SMEM_TOTAL>>>(out, 3);
    }
}